// round 3
// baseline (speedup 1.0000x reference)
#include <cuda_runtime.h>
#include <cstdint>

#define D_   256
#define Z_   32
#define B_   128
#define T_   1000
#define EPS_ 1e-6f
#define NOUT ((size_t)B_ * T_ * D_)
#define JPC  160
#define JPAD 164
#define STH  320

__device__ float g_z[(size_t)B_ * T_ * Z_];
__device__ float g_U[(size_t)B_ * T_ * D_];
__device__ float g_kl[64];

__device__ __forceinline__ float tanh_s(float x) {
    float ax = fabsf(x);
    float e = __expf(-2.0f * ax);
    return copysignf((1.0f - e) / (1.0f + e), x);
}
__device__ __forceinline__ uint32_t smem_u32(const void* p) {
    uint32_t a;
    asm("{ .reg .u64 t; cvta.to.shared.u64 t, %1; cvt.u32.u64 %0, t; }" : "=r"(a) : "l"(p));
    return a;
}

// ---- z = tanh(A[:, :Z]) + noise * exp(A[:, Z:]) ----
__global__ __launch_bounds__(256) void z_kernel(const float* __restrict__ A,
                                                const float* __restrict__ nz) {
    int i = blockIdx.x * 256 + threadIdx.x;
    if (i >= B_ * T_ * Z_) return;
    int m = i >> 5, z = i & 31;
    g_z[i] = tanh_s(A[(size_t)m * 64 + z]) + nz[i] * __expf(A[(size_t)m * 64 + 32 + z]);
}

// ---- U = hd@Whd2h^T + z@Wz2h^T + bias : M=128000 N=256 K=288 ----
__global__ __launch_bounds__(256, 1) void u_gemm(const float* __restrict__ hd,
                                                 const float* __restrict__ Wh,
                                                 const float* __restrict__ Wz,
                                                 const float* __restrict__ bias) {
    __shared__ float As[8][128], Bs[8][128];
    int tid = threadIdx.x;
    int mB = blockIdx.y * 128, nB = blockIdx.x * 128;
    int lr = tid >> 1, lk = (tid & 1) << 2;
    int tr = (tid >> 4) << 3, tc = (tid & 15) << 3;
    float acc[8][8];
#pragma unroll
    for (int i = 0; i < 8; i++)
#pragma unroll
        for (int j = 0; j < 8; j++) acc[i][j] = 0.f;

    for (int k0 = 0; k0 < 288; k0 += 8) {
        float4 av, bv;
        if (k0 < 256) {
            av = *(const float4*)(hd + (size_t)(mB + lr) * 256 + k0 + lk);
            bv = *(const float4*)(Wh + (size_t)(nB + lr) * 256 + k0 + lk);
        } else {
            av = *(const float4*)(g_z + (size_t)(mB + lr) * 32 + (k0 - 256) + lk);
            bv = *(const float4*)(Wz + (size_t)(nB + lr) * 32 + (k0 - 256) + lk);
        }
        __syncthreads();
        As[lk][lr] = av.x; As[lk + 1][lr] = av.y; As[lk + 2][lr] = av.z; As[lk + 3][lr] = av.w;
        Bs[lk][lr] = bv.x; Bs[lk + 1][lr] = bv.y; Bs[lk + 2][lr] = bv.z; Bs[lk + 3][lr] = bv.w;
        __syncthreads();
#pragma unroll
        for (int kk = 0; kk < 8; kk++) {
            float mf[8], nf[8];
            *(float4*)mf = *(const float4*)&As[kk][tr];
            *(float4*)(mf + 4) = *(const float4*)&As[kk][tr + 4];
            *(float4*)nf = *(const float4*)&Bs[kk][tc];
            *(float4*)(nf + 4) = *(const float4*)&Bs[kk][tc + 4];
#pragma unroll
            for (int i = 0; i < 8; i++)
#pragma unroll
                for (int j = 0; j < 8; j++) acc[i][j] += mf[i] * nf[j];
        }
    }
    float bj[8];
#pragma unroll
    for (int j = 0; j < 8; j++) bj[j] = bias[nB + tc + j];
#pragma unroll
    for (int i = 0; i < 8; i++) {
        float* o = g_U + (size_t)(mB + tr + i) * 256 + nB + tc;
#pragma unroll
        for (int j = 0; j < 8; j++) o[j] = acc[i][j] + bj[j];
    }
}

// ---- wnll_init_h ----
__global__ __launch_bounds__(256) void wnll_kernel(const float* __restrict__ ih,
                                                   const float* __restrict__ mu,
                                                   float* __restrict__ out) {
    __shared__ float sr[8];
    int tid = threadIdx.x;
    float s = 0.f;
    for (int i = tid; i < B_ * D_; i += 256) {
        float d = ih[i] - mu[i & 255];
        s += 0.5f * d * d + 0.91893853320467274f;
    }
#pragma unroll
    for (int o = 16; o > 0; o >>= 1) s += __shfl_down_sync(~0u, s, o);
    if ((tid & 31) == 0) sr[tid >> 5] = s;
    __syncthreads();
    if (tid == 0) {
        float t = 0.f;
        for (int i = 0; i < 8; i++) t += sr[i];
        out[NOUT + 1] = 0.001f * t / 256.0f;
    }
}

// ---- kl final reduce ----
__global__ void kl_final(float* __restrict__ out) {
    if (threadIdx.x == 0) {
        float s = 0.f;
        for (int i = 0; i < 64; i++) s += g_kl[i];
        out[NOUT] = 0.001f / 32.0f * s;
    }
}

// ---- sequential scan: 64 clusters x 2 CTAs, 2 batch rows per cluster ----
__global__ void __cluster_dims__(2, 1, 1) __launch_bounds__(STH, 1)
seq_kernel(const float* __restrict__ A, const float* __restrict__ in_p0,
           const float* __restrict__ Wd2h, const float* __restrict__ Wd2z,
           const float* __restrict__ initH, float* __restrict__ out) {
    extern __shared__ float sm[];
    float* Ws   = sm;                 // [256][JPAD] k-major
    float* dbuf = Ws + 256 * JPAD;    // [2][2][256]
    float* red  = dbuf + 1024;        // [8][40][2][4]
    float* dzs  = red + 2560;         // [2][64]

    const int tid = threadIdx.x;
    const int rank = blockIdx.x & 1;
    const int c = blockIdx.x >> 1;

    const int jg = tid % 40, ks = tid / 40, kb = ks * 32;
    const int uj = tid % JPC, ub = tid / JPC;
    const int ng = rank * JPC + uj;
    const bool has_h = (ng < 256);
    const int b_u = 2 * c + ub;
    const float dec = (ng < 128) ? 0.75f : 0.5f;
    const float itau = (ng < 128) ? 0.25f : 0.5f;

    const bool isKL = (rank == 1) && (tid < 64);
    const int klb = tid >> 5, klz = tid & 31;
    float p0m = 0.f, p0s = 0.f;
    const float* Ap = A + (size_t)(2 * c + klb) * T_ * 64;
    if (isKL) {
        p0m = in_p0[(2 * c + klb) * 64 + klz];
        p0s = in_p0[(2 * c + klb) * 64 + 32 + klz];
    }

    for (int i = tid; i < JPC * 256; i += STH) {
        int j = i >> 8, k = i & 255, n = rank * JPC + j;
        Ws[k * JPAD + j] = (n < 256) ? Wd2h[n * 256 + k] : Wd2z[(n - 256) * 256 + k];
    }
    for (int i = tid; i < 512; i += STH) {
        int bb = i >> 8, k = i & 255;
        dbuf[bb * 256 + k] = tanh_s(initH[(2 * c + bb) * 256 + k]);
    }
    float h = 0.f;
    const float* Up = g_U;
    float* Op = out;
    if (has_h) {
        h = initH[b_u * 256 + ng];
        Up = g_U + (size_t)b_u * T_ * 256 + ng;
        Op = out + (size_t)b_u * T_ * 256 + ng;
    }
    const uint32_t dl = smem_u32(dbuf);
    uint32_t dp;
    asm("mapa.shared::cluster.u32 %0, %1, %2;" : "=r"(dp) : "r"(dl), "r"(rank ^ 1));

    asm volatile("barrier.cluster.arrive.aligned;\n\tbarrier.cluster.wait.aligned;" ::: "memory");

    float klacc = 0.f;
    int cur = 0;
    for (int t = 0; t < T_; ++t) {
        float u_pf = has_h ? __ldg(Up) : 0.f;
        float amu = 0.f, als = 0.f;
        if (isKL) { amu = __ldg(Ap + klz); als = __ldg(Ap + 32 + klz); }

        const float* dc = dbuf + cur * 512;
        float a0 = 0, a1 = 0, a2 = 0, a3 = 0, b0 = 0, b1 = 0, b2 = 0, b3 = 0;
        const float4* wr = (const float4*)(Ws + kb * JPAD) + jg;
#pragma unroll 8
        for (int k = 0; k < 32; ++k) {
            float4 w = wr[k * (JPAD / 4)];
            float d0 = dc[kb + k], d1 = dc[256 + kb + k];
            a0 += w.x * d0; a1 += w.y * d0; a2 += w.z * d0; a3 += w.w * d0;
            b0 += w.x * d1; b1 += w.y * d1; b2 += w.z * d1; b3 += w.w * d1;
        }
        float4* r4 = (float4*)red + ((size_t)ks * 40 + jg) * 2;
        r4[0] = make_float4(a0, a1, a2, a3);
        r4[1] = make_float4(b0, b1, b2, b3);
        __syncthreads();

        float f = 0.f;
        const float* rp = red + (uj >> 2) * 8 + ub * 4 + (uj & 3);
#pragma unroll
        for (int s = 0; s < 8; ++s) f += rp[s * 320];

        int nxt = cur ^ 1;
        if (has_h) {
            h = dec * h + itau * (f + u_pf);
            float dn = tanh_s(h);
            int off = nxt * 512 + ub * 256 + ng;
            dbuf[off] = dn;
            asm volatile("st.shared::cluster.b32 [%0], %1;" :: "r"(dp + off * 4),
                         "r"(__float_as_uint(dn)) : "memory");
            *Op = dn;
            Up += 256; Op += 256;
        } else {
            dzs[ub * 64 + (uj - 96)] = f;
        }

        if (rank == 1) {
            __syncthreads();
            if (tid < 64) {
                float mq = tanh_s(amu), sq = __expf(als);
                float pm = (t == 0) ? p0m : dzs[klb * 64 + klz];
                float ps = (t == 0) ? p0s : dzs[klb * 64 + 32 + klz];
                float mp = tanh_s(pm), sp = __expf(ps);
                float dm = mq - mp;
                klacc += __logf(sp + EPS_) - __logf(sq + EPS_) - 0.5f
                       + 0.5f * (dm * dm + sq * sq) / (sp * sp + EPS_);
            }
            Ap += 64;
        }
        cur = nxt;
        asm volatile("barrier.cluster.arrive.aligned;\n\tbarrier.cluster.wait.aligned;" ::: "memory");
    }

    if (rank == 1) {
        if (tid < 64) red[tid] = klacc;
        __syncthreads();
        if (tid == 0) {
            float s = 0.f;
            for (int i = 0; i < 64; i++) s += red[i];
            g_kl[c] = s;
        }
    }
}

extern "C" void kernel_launch(void* const* d_in, const int* in_sizes, int n_in,
                              void* d_out, int out_size) {
    const float* hd    = (const float*)d_in[0];
    const float* A     = (const float*)d_in[1];
    const float* in_p0 = (const float*)d_in[2];
    const float* noise = (const float*)d_in[3];
    const float* Wd2h  = (const float*)d_in[4];
    const float* Wz2h  = (const float*)d_in[5];
    const float* Wd2z  = (const float*)d_in[6];
    const float* Whd2h = (const float*)d_in[7];
    const float* biasd = (const float*)d_in[8];
    const float* initH = (const float*)d_in[9];
    const float* ihmu  = (const float*)d_in[10];
    float* out = (float*)d_out;

    z_kernel<<<(B_ * T_ * Z_ + 255) / 256, 256>>>(A, noise);
    u_gemm<<<dim3(2, 1000), 256>>>(hd, Whd2h, Wz2h, biasd);
    wnll_kernel<<<1, 256>>>(initH, ihmu, out);

    const int smem = (256 * JPAD + 1024 + 2560 + 128) * 4;
    cudaFuncSetAttribute(seq_kernel, cudaFuncAttributeMaxDynamicSharedMemorySize, smem);
    seq_kernel<<<128, STH, smem>>>(A, in_p0, Wd2h, Wd2z, initH, out);
    kl_final<<<1, 32>>>(out);
}